// round 3
// baseline (speedup 1.0000x reference)
#include <cuda_runtime.h>
#include <math.h>

#define N_NODES 50000
#define N_EDGES 1600000
#define FEAT 256
#define HID 256
#define OUTD 64

// ---------------- scratch (device globals; no allocation) ----------------
__device__ int   g_cnt[N_NODES];          // histogram, then scatter cursor
__device__ int   g_rowptr[N_NODES + 1];
__device__ int   g_cols[N_EDGES];
__device__ float g_wr[N_EDGES];
__device__ float g_wi[N_EDGES];
__device__ float g_Sr[N_NODES * FEAT];    // SPMM outputs (GEMM inputs)
__device__ float g_Si[N_NODES * FEAT];
__device__ float g_Hr[N_NODES * FEAT];    // layer activations
__device__ float g_Hi[N_NODES * FEAT];

// ---------------- 0) zero histogram ----------------
__global__ void zero_kernel() {
    int i = blockIdx.x * blockDim.x + threadIdx.x;
    if (i < N_NODES) g_cnt[i] = 0;
}

// ---------------- 1) histogram of dst (row) ----------------
__global__ void hist_kernel(const int* __restrict__ row) {
    int e = blockIdx.x * blockDim.x + threadIdx.x;
    if (e < N_EDGES) atomicAdd(&g_cnt[row[e]], 1);
}

// ---------------- 2) exclusive scan (single block) ----------------
__global__ void scan_kernel() {
    __shared__ int s[1024];
    __shared__ int carry;
    int t = threadIdx.x;
    if (t == 0) carry = 0;
    __syncthreads();
    for (int base = 0; base < N_NODES; base += 1024) {
        int idx = base + t;
        int v = (idx < N_NODES) ? g_cnt[idx] : 0;
        s[t] = v;
        __syncthreads();
        for (int off = 1; off < 1024; off <<= 1) {
            int x = (t >= off) ? s[t - off] : 0;
            __syncthreads();
            s[t] += x;
            __syncthreads();
        }
        int excl = s[t] - v + carry;
        if (idx < N_NODES) { g_rowptr[idx] = excl; g_cnt[idx] = excl; }  // cursor = seg start
        int tot = s[1023];
        __syncthreads();
        if (t == 0) carry += tot;
        __syncthreads();
    }
    if (t == 0) g_rowptr[N_NODES] = carry;
}

// ---------------- 3) edge weights + scatter into dst-sorted arrays ----------------
__global__ void scatter_kernel(const int* __restrict__ row, const int* __restrict__ col,
                               const float* __restrict__ ews, const float* __restrict__ ent,
                               const float* __restrict__ ccf, const float* __restrict__ q) {
    int e = blockIdx.x * blockDim.x + threadIdx.x;
    if (e >= N_EDGES) return;
    float phase = q[0] * (ent[e] + ccf[e]);
    float sn, cs;
    sincosf(phase, &sn, &cs);
    float w = ews[e];
    int pos = atomicAdd(&g_cnt[row[e]], 1);
    g_cols[pos] = col[e];
    g_wr[pos]   = w * cs;
    g_wi[pos]   = w * sn;
}

// ---------------- 4) complex SPMM: S = A_complex @ X_complex ----------------
// 4 nodes per block, 64 threads (float4 lanes) per node.
__global__ void __launch_bounds__(256) spmm_kernel(const float* __restrict__ Xr,
                                                   const float* __restrict__ Xi,
                                                   float* __restrict__ Sr,
                                                   float* __restrict__ Si) {
    int node = blockIdx.x * 4 + threadIdx.y;
    if (node >= N_NODES) return;
    int t = threadIdx.x;  // 0..63
    const float4* Xr4 = (const float4*)Xr;
    const float4* Xi4 = (const float4*)Xi;
    float4 ar = make_float4(0.f, 0.f, 0.f, 0.f);
    float4 ai = make_float4(0.f, 0.f, 0.f, 0.f);
    int e = g_rowptr[node];
    int end = g_rowptr[node + 1];
#pragma unroll 2
    for (; e < end; e++) {
        int   c  = __ldg(&g_cols[e]);
        float wr = __ldg(&g_wr[e]);
        float wi = __ldg(&g_wi[e]);
        float4 xr = __ldg(&Xr4[c * 64 + t]);
        float4 xi = __ldg(&Xi4[c * 64 + t]);
        ar.x = fmaf(wr, xr.x, ar.x); ar.x = fmaf(-wi, xi.x, ar.x);
        ar.y = fmaf(wr, xr.y, ar.y); ar.y = fmaf(-wi, xi.y, ar.y);
        ar.z = fmaf(wr, xr.z, ar.z); ar.z = fmaf(-wi, xi.z, ar.z);
        ar.w = fmaf(wr, xr.w, ar.w); ar.w = fmaf(-wi, xi.w, ar.w);
        ai.x = fmaf(wi, xr.x, ai.x); ai.x = fmaf(wr, xi.x, ai.x);
        ai.y = fmaf(wi, xr.y, ai.y); ai.y = fmaf(wr, xi.y, ai.y);
        ai.z = fmaf(wi, xr.z, ai.z); ai.z = fmaf(wr, xi.z, ai.z);
        ai.w = fmaf(wi, xr.w, ai.w); ai.w = fmaf(wr, xi.w, ai.w);
    }
    ((float4*)Sr)[node * 64 + t] = ar;
    ((float4*)Si)[node * 64 + t] = ai;
}

// ---------------- 5) SGEMM (NT): C[m,n] = sum_k A[m,k] * W[n,k], K=N=256 ----------------
#define GBM 128
#define GBN 128
#define GBK 16

__global__ void __launch_bounds__(256) gemm_real_kernel(const float* __restrict__ A,
                                                        const float* __restrict__ W,
                                                        float* __restrict__ C, int M) {
    __shared__ __align__(16) float As[GBK][GBM];
    __shared__ __align__(16) float Bs[GBK][GBN];
    const int K = 256;
    int tid = threadIdx.x;
    int m_base = blockIdx.x * GBM;
    int n_base = blockIdx.y * GBN;
    int tx = tid & 15, ty = tid >> 4;
    int m0 = ty * 8, n0 = tx * 8;
    float acc[8][8];
#pragma unroll
    for (int i = 0; i < 8; i++)
#pragma unroll
        for (int j = 0; j < 8; j++) acc[i][j] = 0.f;

    for (int k0 = 0; k0 < K; k0 += GBK) {
#pragma unroll
        for (int it = 0; it < 2; it++) {
            int idx = tid + it * 256;
            int r = idx >> 2, kq = idx & 3;
            int gm = m_base + r;
            float4 v = make_float4(0.f, 0.f, 0.f, 0.f);
            if (gm < M) v = *(const float4*)&A[gm * K + k0 + kq * 4];
            As[kq * 4 + 0][r] = v.x; As[kq * 4 + 1][r] = v.y;
            As[kq * 4 + 2][r] = v.z; As[kq * 4 + 3][r] = v.w;
        }
#pragma unroll
        for (int it = 0; it < 2; it++) {
            int idx = tid + it * 256;
            int r = idx >> 2, kq = idx & 3;
            float4 v = *(const float4*)&W[(n_base + r) * K + k0 + kq * 4];
            Bs[kq * 4 + 0][r] = v.x; Bs[kq * 4 + 1][r] = v.y;
            Bs[kq * 4 + 2][r] = v.z; Bs[kq * 4 + 3][r] = v.w;
        }
        __syncthreads();
#pragma unroll
        for (int k = 0; k < GBK; k++) {
            float a[8], b[8];
            *(float4*)&a[0] = *(const float4*)&As[k][m0];
            *(float4*)&a[4] = *(const float4*)&As[k][m0 + 4];
            *(float4*)&b[0] = *(const float4*)&Bs[k][n0];
            *(float4*)&b[4] = *(const float4*)&Bs[k][n0 + 4];
#pragma unroll
            for (int i = 0; i < 8; i++)
#pragma unroll
                for (int j = 0; j < 8; j++) acc[i][j] = fmaf(a[i], b[j], acc[i][j]);
        }
        __syncthreads();
    }
#pragma unroll
    for (int i = 0; i < 8; i++) {
        int gm = m_base + m0 + i;
        if (gm < M) {
#pragma unroll
            for (int jq = 0; jq < 2; jq++) {
                float4 v = make_float4(acc[i][jq * 4 + 0], acc[i][jq * 4 + 1],
                                       acc[i][jq * 4 + 2], acc[i][jq * 4 + 3]);
                *(float4*)&C[gm * 256 + n_base + n0 + jq * 4] = v;
            }
        }
    }
}

// imag GEMM + comrelu mask epilogue:
// Pi = Ai@W^T + 2b ; pr = Cr (pre-act real) ; mask = pr>=0 ; Cr=pr*mask (in place) ; Ci=Pi*mask
__global__ void __launch_bounds__(256) gemm_imag_mask_kernel(const float* __restrict__ Ai,
                                                             const float* __restrict__ W,
                                                             const float* __restrict__ bias,
                                                             float* __restrict__ Cr,
                                                             float* __restrict__ Ci, int M) {
    __shared__ __align__(16) float As[GBK][GBM];
    __shared__ __align__(16) float Bs[GBK][GBN];
    const int K = 256;
    int tid = threadIdx.x;
    int m_base = blockIdx.x * GBM;
    int n_base = blockIdx.y * GBN;
    int tx = tid & 15, ty = tid >> 4;
    int m0 = ty * 8, n0 = tx * 8;
    float acc[8][8];
#pragma unroll
    for (int i = 0; i < 8; i++)
#pragma unroll
        for (int j = 0; j < 8; j++) acc[i][j] = 0.f;

    for (int k0 = 0; k0 < K; k0 += GBK) {
#pragma unroll
        for (int it = 0; it < 2; it++) {
            int idx = tid + it * 256;
            int r = idx >> 2, kq = idx & 3;
            int gm = m_base + r;
            float4 v = make_float4(0.f, 0.f, 0.f, 0.f);
            if (gm < M) v = *(const float4*)&Ai[gm * K + k0 + kq * 4];
            As[kq * 4 + 0][r] = v.x; As[kq * 4 + 1][r] = v.y;
            As[kq * 4 + 2][r] = v.z; As[kq * 4 + 3][r] = v.w;
        }
#pragma unroll
        for (int it = 0; it < 2; it++) {
            int idx = tid + it * 256;
            int r = idx >> 2, kq = idx & 3;
            float4 v = *(const float4*)&W[(n_base + r) * K + k0 + kq * 4];
            Bs[kq * 4 + 0][r] = v.x; Bs[kq * 4 + 1][r] = v.y;
            Bs[kq * 4 + 2][r] = v.z; Bs[kq * 4 + 3][r] = v.w;
        }
        __syncthreads();
#pragma unroll
        for (int k = 0; k < GBK; k++) {
            float a[8], b[8];
            *(float4*)&a[0] = *(const float4*)&As[k][m0];
            *(float4*)&a[4] = *(const float4*)&As[k][m0 + 4];
            *(float4*)&b[0] = *(const float4*)&Bs[k][n0];
            *(float4*)&b[4] = *(const float4*)&Bs[k][n0 + 4];
#pragma unroll
            for (int i = 0; i < 8; i++)
#pragma unroll
                for (int j = 0; j < 8; j++) acc[i][j] = fmaf(a[i], b[j], acc[i][j]);
        }
        __syncthreads();
    }
#pragma unroll
    for (int i = 0; i < 8; i++) {
        int gm = m_base + m0 + i;
        if (gm < M) {
#pragma unroll
            for (int jq = 0; jq < 2; jq++) {
                int gn = n_base + n0 + jq * 4;
                float4 pr = *(const float4*)&Cr[gm * 256 + gn];
                float4 bb = *(const float4*)&bias[gn];
                float pi0 = acc[i][jq * 4 + 0] + 2.f * bb.x;
                float pi1 = acc[i][jq * 4 + 1] + 2.f * bb.y;
                float pi2 = acc[i][jq * 4 + 2] + 2.f * bb.z;
                float pi3 = acc[i][jq * 4 + 3] + 2.f * bb.w;
                float m0f = (pr.x >= 0.f) ? 1.f : 0.f;
                float m1f = (pr.y >= 0.f) ? 1.f : 0.f;
                float m2f = (pr.z >= 0.f) ? 1.f : 0.f;
                float m3f = (pr.w >= 0.f) ? 1.f : 0.f;
                float4 outr = make_float4(pr.x * m0f, pr.y * m1f, pr.z * m2f, pr.w * m3f);
                float4 outi = make_float4(pi0 * m0f, pi1 * m1f, pi2 * m2f, pi3 * m3f);
                *(float4*)&Cr[gm * 256 + gn] = outr;
                *(float4*)&Ci[gm * 256 + gn] = outi;
            }
        }
    }
}

// ---------------- 6) head: out = [Hr|Hi] @ W3^T + b3 ; M x 512 x 64 ----------------
#define HBM 128
#define HBN 64
#define HBK 16
__global__ void __launch_bounds__(256) head_kernel(const float* __restrict__ Ar,
                                                   const float* __restrict__ Ai,
                                                   const float* __restrict__ W,
                                                   const float* __restrict__ bias,
                                                   float* __restrict__ Cout, int M) {
    __shared__ __align__(16) float As[HBK][HBM];
    __shared__ __align__(16) float Bs[HBK][HBN];
    int tid = threadIdx.x;
    int m_base = blockIdx.x * HBM;
    int tx = tid & 15, ty = tid >> 4;
    int m0 = ty * 8, n0 = tx * 4;
    float acc[8][4];
#pragma unroll
    for (int i = 0; i < 8; i++)
#pragma unroll
        for (int j = 0; j < 4; j++) acc[i][j] = 0.f;

    for (int k0 = 0; k0 < 512; k0 += HBK) {
        const float* Asrc = (k0 < 256) ? Ar : Ai;
        int koff = k0 & 255;
#pragma unroll
        for (int it = 0; it < 2; it++) {
            int idx = tid + it * 256;
            int r = idx >> 2, kq = idx & 3;
            int gm = m_base + r;
            float4 v = make_float4(0.f, 0.f, 0.f, 0.f);
            if (gm < M) v = *(const float4*)&Asrc[gm * 256 + koff + kq * 4];
            As[kq * 4 + 0][r] = v.x; As[kq * 4 + 1][r] = v.y;
            As[kq * 4 + 2][r] = v.z; As[kq * 4 + 3][r] = v.w;
        }
        {
            int idx = tid;  // 256 threads cover 64x16/4 = 256 float4 loads
            int r = idx >> 2, kq = idx & 3;
            float4 v = *(const float4*)&W[r * 512 + k0 + kq * 4];
            Bs[kq * 4 + 0][r] = v.x; Bs[kq * 4 + 1][r] = v.y;
            Bs[kq * 4 + 2][r] = v.z; Bs[kq * 4 + 3][r] = v.w;
        }
        __syncthreads();
#pragma unroll
        for (int k = 0; k < HBK; k++) {
            float a[8], b[4];
            *(float4*)&a[0] = *(const float4*)&As[k][m0];
            *(float4*)&a[4] = *(const float4*)&As[k][m0 + 4];
            *(float4*)&b[0] = *(const float4*)&Bs[k][n0];
#pragma unroll
            for (int i = 0; i < 8; i++)
#pragma unroll
                for (int j = 0; j < 4; j++) acc[i][j] = fmaf(a[i], b[j], acc[i][j]);
        }
        __syncthreads();
    }
    float4 bb = *(const float4*)&bias[n0];
#pragma unroll
    for (int i = 0; i < 8; i++) {
        int gm = m_base + m0 + i;
        if (gm < M) {
            float4 v = make_float4(acc[i][0] + bb.x, acc[i][1] + bb.y,
                                   acc[i][2] + bb.z, acc[i][3] + bb.w);
            *(float4*)&Cout[gm * OUTD + n0] = v;
        }
    }
}

// ---------------- launch ----------------
extern "C" void kernel_launch(void* const* d_in, const int* in_sizes, int n_in,
                              void* d_out, int out_size) {
    const float* real_feature = (const float*)d_in[0];
    const float* imag_feature = (const float*)d_in[1];
    const int*   row          = (const int*)d_in[2];
    const int*   col          = (const int*)d_in[3];
    const float* ews          = (const float*)d_in[4];
    const float* ent          = (const float*)d_in[5];
    const float* ccf          = (const float*)d_in[6];
    const float* q            = (const float*)d_in[7];
    const float* W1           = (const float*)d_in[8];
    const float* b1           = (const float*)d_in[9];
    const float* W2           = (const float*)d_in[10];
    const float* b2           = (const float*)d_in[11];
    const float* W3           = (const float*)d_in[12];
    const float* b3           = (const float*)d_in[13];
    float* outp = (float*)d_out;

    float *pSr, *pSi, *pHr, *pHi;
    cudaGetSymbolAddress((void**)&pSr, g_Sr);
    cudaGetSymbolAddress((void**)&pSi, g_Si);
    cudaGetSymbolAddress((void**)&pHr, g_Hr);
    cudaGetSymbolAddress((void**)&pHi, g_Hi);

    const int M = N_NODES;
    dim3 gemm_grid((M + GBM - 1) / GBM, 2);
    dim3 head_grid((M + HBM - 1) / HBM, 1);
    dim3 spmm_grid((N_NODES + 3) / 4);
    dim3 spmm_block(64, 4);

    // build dst-sorted CSR each launch (graph-capturable, deterministic structure)
    zero_kernel<<<(N_NODES + 255) / 256, 256>>>();
    hist_kernel<<<(N_EDGES + 255) / 256, 256>>>(row);
    scan_kernel<<<1, 1024>>>();
    scatter_kernel<<<(N_EDGES + 255) / 256, 256>>>(row, col, ews, ent, ccf, q);

    // layer 1
    spmm_kernel<<<spmm_grid, spmm_block>>>(real_feature, imag_feature, pSr, pSi);
    gemm_real_kernel<<<gemm_grid, 256>>>(pSr, W1, pHr, M);
    gemm_imag_mask_kernel<<<gemm_grid, 256>>>(pSi, W1, b1, pHr, pHi, M);

    // layer 2
    spmm_kernel<<<spmm_grid, spmm_block>>>(pHr, pHi, pSr, pSi);
    gemm_real_kernel<<<gemm_grid, 256>>>(pSr, W2, pHr, M);
    gemm_imag_mask_kernel<<<gemm_grid, 256>>>(pSi, W2, b2, pHr, pHi, M);

    // head
    head_kernel<<<head_grid, 256>>>(pHr, pHi, W3, b3, outp, M);
}

// round 11
// speedup vs baseline: 1.0165x; 1.0165x over previous
#include <cuda_runtime.h>
#include <cstdint>
#include <math.h>

#define N_NODES 50000
#define N_EDGES 1600000
#define FEAT 256
#define HID 256
#define OUTD 64

typedef unsigned long long ull;

// ---------- packed dual-fp32 FMA (FFMA2) ----------
__device__ __forceinline__ void ffma2(ull& c, ull a, ull b) {
    asm("fma.rn.f32x2 %0, %1, %2, %0;" : "+l"(c) : "l"(a), "l"(b));
}
__device__ __forceinline__ ull bcast2(float x) {
    ull r;
    unsigned u = __float_as_uint(x);
    asm("mov.b64 %0, {%1, %1};" : "=l"(r) : "r"(u));
    return r;
}
__device__ __forceinline__ float2 unpack2(ull x) {
    float2 f;
    asm("mov.b64 {%0, %1}, %2;" : "=f"(f.x), "=f"(f.y) : "l"(x));
    return f;
}

// ---------------- scratch (device globals; no allocation) ----------------
__device__ int   g_cnt[N_NODES];
__device__ int   g_rowptr[N_NODES + 1];
__device__ int   g_cols[N_EDGES];
__device__ float g_wr[N_EDGES];
__device__ float g_wi[N_EDGES];
__device__ float g_Sr[N_NODES * FEAT];
__device__ float g_Si[N_NODES * FEAT];
__device__ float g_Hr[N_NODES * FEAT];
__device__ float g_Hi[N_NODES * FEAT];

// ---------------- CSR build ----------------
__global__ void zero_kernel() {
    int i = blockIdx.x * blockDim.x + threadIdx.x;
    if (i < N_NODES) g_cnt[i] = 0;
}
__global__ void hist_kernel(const int* __restrict__ row) {
    int e = blockIdx.x * blockDim.x + threadIdx.x;
    if (e < N_EDGES) atomicAdd(&g_cnt[row[e]], 1);
}
__global__ void scan_kernel() {
    __shared__ int s[1024];
    __shared__ int carry;
    int t = threadIdx.x;
    if (t == 0) carry = 0;
    __syncthreads();
    for (int base = 0; base < N_NODES; base += 1024) {
        int idx = base + t;
        int v = (idx < N_NODES) ? g_cnt[idx] : 0;
        s[t] = v;
        __syncthreads();
        for (int off = 1; off < 1024; off <<= 1) {
            int x = (t >= off) ? s[t - off] : 0;
            __syncthreads();
            s[t] += x;
            __syncthreads();
        }
        int excl = s[t] - v + carry;
        if (idx < N_NODES) { g_rowptr[idx] = excl; g_cnt[idx] = excl; }
        int tot = s[1023];
        __syncthreads();
        if (t == 0) carry += tot;
        __syncthreads();
    }
    if (t == 0) g_rowptr[N_NODES] = carry;
}
__global__ void scatter_kernel(const int* __restrict__ row, const int* __restrict__ col,
                               const float* __restrict__ ews, const float* __restrict__ ent,
                               const float* __restrict__ ccf, const float* __restrict__ q) {
    int e = blockIdx.x * blockDim.x + threadIdx.x;
    if (e >= N_EDGES) return;
    float phase = q[0] * (ent[e] + ccf[e]);
    float sn, cs;
    sincosf(phase, &sn, &cs);
    float w = ews[e];
    int pos = atomicAdd(&g_cnt[row[e]], 1);
    g_cols[pos] = col[e];
    g_wr[pos]   = w * cs;
    g_wi[pos]   = w * sn;
}

// ---------------- complex SPMM ----------------
__global__ void __launch_bounds__(256) spmm_kernel(const float* __restrict__ Xr,
                                                   const float* __restrict__ Xi,
                                                   float* __restrict__ Sr,
                                                   float* __restrict__ Si) {
    int node = blockIdx.x * 4 + threadIdx.y;
    if (node >= N_NODES) return;
    int t = threadIdx.x;  // 0..63
    const float4* Xr4 = (const float4*)Xr;
    const float4* Xi4 = (const float4*)Xi;
    float4 ar = make_float4(0.f, 0.f, 0.f, 0.f);
    float4 ai = make_float4(0.f, 0.f, 0.f, 0.f);
    int e = g_rowptr[node];
    int end = g_rowptr[node + 1];
#pragma unroll 2
    for (; e < end; e++) {
        int   c  = __ldg(&g_cols[e]);
        float wr = __ldg(&g_wr[e]);
        float wi = __ldg(&g_wi[e]);
        float4 xr = __ldg(&Xr4[c * 64 + t]);
        float4 xi = __ldg(&Xi4[c * 64 + t]);
        ar.x = fmaf(wr, xr.x, ar.x); ar.x = fmaf(-wi, xi.x, ar.x);
        ar.y = fmaf(wr, xr.y, ar.y); ar.y = fmaf(-wi, xi.y, ar.y);
        ar.z = fmaf(wr, xr.z, ar.z); ar.z = fmaf(-wi, xi.z, ar.z);
        ar.w = fmaf(wr, xr.w, ar.w); ar.w = fmaf(-wi, xi.w, ar.w);
        ai.x = fmaf(wi, xr.x, ai.x); ai.x = fmaf(wr, xi.x, ai.x);
        ai.y = fmaf(wi, xr.y, ai.y); ai.y = fmaf(wr, xi.y, ai.y);
        ai.z = fmaf(wi, xr.z, ai.z); ai.z = fmaf(wr, xi.z, ai.z);
        ai.w = fmaf(wi, xr.w, ai.w); ai.w = fmaf(wr, xi.w, ai.w);
    }
    ((float4*)Sr)[node * 64 + t] = ar;
    ((float4*)Si)[node * 64 + t] = ai;
}

// ---------------- SGEMM (NT) with FFMA2: C[m,n] = sum_k A[m,k] * W[n,k] ----------------
#define GBM 128
#define GBN 128
#define GBK 16

__device__ __forceinline__ void load_tiles(float (*As)[GBM], float (*Bs)[GBN],
                                           const float* __restrict__ A,
                                           const float* __restrict__ W,
                                           int m_base, int n_base, int k0, int M, int tid) {
    const int K = 256;
#pragma unroll
    for (int it = 0; it < 2; it++) {
        int idx = tid + it * 256;
        int r = idx >> 2, kq = idx & 3;
        int gm = m_base + r;
        float4 v = make_float4(0.f, 0.f, 0.f, 0.f);
        if (gm < M) v = *(const float4*)&A[gm * K + k0 + kq * 4];
        As[kq * 4 + 0][r] = v.x; As[kq * 4 + 1][r] = v.y;
        As[kq * 4 + 2][r] = v.z; As[kq * 4 + 3][r] = v.w;
    }
#pragma unroll
    for (int it = 0; it < 2; it++) {
        int idx = tid + it * 256;
        int r = idx >> 2, kq = idx & 3;
        float4 v = *(const float4*)&W[(n_base + r) * K + k0 + kq * 4];
        Bs[kq * 4 + 0][r] = v.x; Bs[kq * 4 + 1][r] = v.y;
        Bs[kq * 4 + 2][r] = v.z; Bs[kq * 4 + 3][r] = v.w;
    }
}

__device__ __forceinline__ void tile_compute(const float (*As)[GBM], const float (*Bs)[GBN],
                                             int m0, int n0, ull acc[8][4]) {
#pragma unroll
    for (int k = 0; k < GBK; k++) {
        float a[8];
        *(float4*)&a[0] = *(const float4*)&As[k][m0];
        *(float4*)&a[4] = *(const float4*)&As[k][m0 + 4];
        ulonglong2 bA = *(const ulonglong2*)&Bs[k][n0];
        ulonglong2 bB = *(const ulonglong2*)&Bs[k][n0 + 4];
#pragma unroll
        for (int i = 0; i < 8; i++) {
            ull ai = bcast2(a[i]);
            ffma2(acc[i][0], ai, bA.x);
            ffma2(acc[i][1], ai, bA.y);
            ffma2(acc[i][2], ai, bB.x);
            ffma2(acc[i][3], ai, bB.y);
        }
    }
}

// real part: write pre-activation Pr to C (=Hr)
__global__ void __launch_bounds__(256) gemm_real_kernel(const float* __restrict__ A,
                                                        const float* __restrict__ W,
                                                        float* __restrict__ C, int M) {
    __shared__ __align__(16) float As[GBK][GBM];
    __shared__ __align__(16) float Bs[GBK][GBN];
    int tid = threadIdx.x;
    int m_base = blockIdx.x * GBM;
    int n_base = blockIdx.y * GBN;
    int tx = tid & 15, ty = tid >> 4;
    int m0 = ty * 8, n0 = tx * 8;
    ull acc[8][4];
#pragma unroll
    for (int i = 0; i < 8; i++)
#pragma unroll
        for (int j = 0; j < 4; j++) acc[i][j] = 0ull;

    for (int k0 = 0; k0 < 256; k0 += GBK) {
        load_tiles(As, Bs, A, W, m_base, n_base, k0, M, tid);
        __syncthreads();
        tile_compute(As, Bs, m0, n0, acc);
        __syncthreads();
    }
#pragma unroll
    for (int i = 0; i < 8; i++) {
        int gm = m_base + m0 + i;
        if (gm < M) {
#pragma unroll
            for (int jq = 0; jq < 2; jq++) {
                float2 p0 = unpack2(acc[i][jq * 2 + 0]);
                float2 p1 = unpack2(acc[i][jq * 2 + 1]);
                *(float4*)&C[gm * 256 + n_base + n0 + jq * 4] =
                    make_float4(p0.x, p0.y, p1.x, p1.y);
            }
        }
    }
}

// imag GEMM + ComReLU mask epilogue:
// Pi = Ai@W^T + 2b ; pr = Cr (pre-act real) ; mask = pr>=0 ; Cr=pr*mask ; Ci=Pi*mask
__global__ void __launch_bounds__(256) gemm_imag_mask_kernel(const float* __restrict__ Ai,
                                                             const float* __restrict__ W,
                                                             const float* __restrict__ bias,
                                                             float* __restrict__ Cr,
                                                             float* __restrict__ Ci, int M) {
    __shared__ __align__(16) float As[GBK][GBM];
    __shared__ __align__(16) float Bs[GBK][GBN];
    int tid = threadIdx.x;
    int m_base = blockIdx.x * GBM;
    int n_base = blockIdx.y * GBN;
    int tx = tid & 15, ty = tid >> 4;
    int m0 = ty * 8, n0 = tx * 8;
    ull acc[8][4];
#pragma unroll
    for (int i = 0; i < 8; i++)
#pragma unroll
        for (int j = 0; j < 4; j++) acc[i][j] = 0ull;

    for (int k0 = 0; k0 < 256; k0 += GBK) {
        load_tiles(As, Bs, Ai, W, m_base, n_base, k0, M, tid);
        __syncthreads();
        tile_compute(As, Bs, m0, n0, acc);
        __syncthreads();
    }
#pragma unroll
    for (int i = 0; i < 8; i++) {
        int gm = m_base + m0 + i;
        if (gm < M) {
#pragma unroll
            for (int jq = 0; jq < 2; jq++) {
                int gn = n_base + n0 + jq * 4;
                float2 q0 = unpack2(acc[i][jq * 2 + 0]);
                float2 q1 = unpack2(acc[i][jq * 2 + 1]);
                float4 pr = *(const float4*)&Cr[gm * 256 + gn];
                float4 bb = *(const float4*)&bias[gn];
                float pi0 = q0.x + 2.f * bb.x;
                float pi1 = q0.y + 2.f * bb.y;
                float pi2 = q1.x + 2.f * bb.z;
                float pi3 = q1.y + 2.f * bb.w;
                float m0f = (pr.x >= 0.f) ? 1.f : 0.f;
                float m1f = (pr.y >= 0.f) ? 1.f : 0.f;
                float m2f = (pr.z >= 0.f) ? 1.f : 0.f;
                float m3f = (pr.w >= 0.f) ? 1.f : 0.f;
                *(float4*)&Cr[gm * 256 + gn] =
                    make_float4(pr.x * m0f, pr.y * m1f, pr.z * m2f, pr.w * m3f);
                *(float4*)&Ci[gm * 256 + gn] =
                    make_float4(pi0 * m0f, pi1 * m1f, pi2 * m2f, pi3 * m3f);
            }
        }
    }
}

// ---------------- head: out = [Hr|Hi] @ W3^T + b3 ; M x 512 x 64 ----------------
#define HBM 128
#define HBN 64
#define HBK 16
__global__ void __launch_bounds__(256) head_kernel(const float* __restrict__ Ar,
                                                   const float* __restrict__ Ai,
                                                   const float* __restrict__ W,
                                                   const float* __restrict__ bias,
                                                   float* __restrict__ Cout, int M) {
    __shared__ __align__(16) float As[HBK][HBM];
    __shared__ __align__(16) float Bs[HBK][HBN];
    int tid = threadIdx.x;
    int m_base = blockIdx.x * HBM;
    int tx = tid & 15, ty = tid >> 4;
    int m0 = ty * 8, n0 = tx * 4;
    ull acc[8][2];
#pragma unroll
    for (int i = 0; i < 8; i++) {
        acc[i][0] = 0ull;
        acc[i][1] = 0ull;
    }

    for (int k0 = 0; k0 < 512; k0 += HBK) {
        const float* Asrc = (k0 < 256) ? Ar : Ai;
        int koff = k0 & 255;
#pragma unroll
        for (int it = 0; it < 2; it++) {
            int idx = tid + it * 256;
            int r = idx >> 2, kq = idx & 3;
            int gm = m_base + r;
            float4 v = make_float4(0.f, 0.f, 0.f, 0.f);
            if (gm < M) v = *(const float4*)&Asrc[gm * 256 + koff + kq * 4];
            As[kq * 4 + 0][r] = v.x; As[kq * 4 + 1][r] = v.y;
            As[kq * 4 + 2][r] = v.z; As[kq * 4 + 3][r] = v.w;
        }
        {
            int idx = tid;  // 256 threads cover 64x16/4 = 256 float4 loads
            int r = idx >> 2, kq = idx & 3;
            float4 v = *(const float4*)&W[r * 512 + k0 + kq * 4];
            Bs[kq * 4 + 0][r] = v.x; Bs[kq * 4 + 1][r] = v.y;
            Bs[kq * 4 + 2][r] = v.z; Bs[kq * 4 + 3][r] = v.w;
        }
        __syncthreads();
#pragma unroll
        for (int k = 0; k < HBK; k++) {
            float a[8];
            *(float4*)&a[0] = *(const float4*)&As[k][m0];
            *(float4*)&a[4] = *(const float4*)&As[k][m0 + 4];
            ulonglong2 bA = *(const ulonglong2*)&Bs[k][n0];
#pragma unroll
            for (int i = 0; i < 8; i++) {
                ull ai = bcast2(a[i]);
                ffma2(acc[i][0], ai, bA.x);
                ffma2(acc[i][1], ai, bA.y);
            }
        }
        __syncthreads();
    }
    float4 bb = *(const float4*)&bias[n0];
#pragma unroll
    for (int i = 0; i < 8; i++) {
        int gm = m_base + m0 + i;
        if (gm < M) {
            float2 u0 = unpack2(acc[i][0]);
            float2 u1 = unpack2(acc[i][1]);
            *(float4*)&Cout[gm * OUTD + n0] =
                make_float4(u0.x + bb.x, u0.y + bb.y, u1.x + bb.z, u1.y + bb.w);
        }
    }
}

// ---------------- launch ----------------
extern "C" void kernel_launch(void* const* d_in, const int* in_sizes, int n_in,
                              void* d_out, int out_size) {
    const float* real_feature = (const float*)d_in[0];
    const float* imag_feature = (const float*)d_in[1];
    const int*   row          = (const int*)d_in[2];
    const int*   col          = (const int*)d_in[3];
    const float* ews          = (const float*)d_in[4];
    const float* ent          = (const float*)d_in[5];
    const float* ccf          = (const float*)d_in[6];
    const float* q            = (const float*)d_in[7];
    const float* W1           = (const float*)d_in[8];
    const float* b1           = (const float*)d_in[9];
    const float* W2           = (const float*)d_in[10];
    const float* b2           = (const float*)d_in[11];
    const float* W3           = (const float*)d_in[12];
    const float* b3           = (const float*)d_in[13];
    float* outp = (float*)d_out;

    float *pSr, *pSi, *pHr, *pHi;
    cudaGetSymbolAddress((void**)&pSr, g_Sr);
    cudaGetSymbolAddress((void**)&pSi, g_Si);
    cudaGetSymbolAddress((void**)&pHr, g_Hr);
    cudaGetSymbolAddress((void**)&pHi, g_Hi);

    const int M = N_NODES;
    dim3 gemm_grid((M + GBM - 1) / GBM, 2);
    dim3 head_grid((M + HBM - 1) / HBM, 1);
    dim3 spmm_grid((N_NODES + 3) / 4);
    dim3 spmm_block(64, 4);

    // build dst-sorted CSR each launch
    zero_kernel<<<(N_NODES + 255) / 256, 256>>>();
    hist_kernel<<<(N_EDGES + 255) / 256, 256>>>(row);
    scan_kernel<<<1, 1024>>>();
    scatter_kernel<<<(N_EDGES + 255) / 256, 256>>>(row, col, ews, ent, ccf, q);

    // layer 1
    spmm_kernel<<<spmm_grid, spmm_block>>>(real_feature, imag_feature, pSr, pSi);
    gemm_real_kernel<<<gemm_grid, 256>>>(pSr, W1, pHr, M);
    gemm_imag_mask_kernel<<<gemm_grid, 256>>>(pSi, W1, b1, pHr, pHi, M);

    // layer 2
    spmm_kernel<<<spmm_grid, spmm_block>>>(pHr, pHi, pSr, pSi);
    gemm_real_kernel<<<gemm_grid, 256>>>(pSr, W2, pHr, M);
    gemm_imag_mask_kernel<<<gemm_grid, 256>>>(pSi, W2, b2, pHr, pHi, M);

    // head
    head_kernel<<<head_grid, 256>>>(pHr, pHi, W3, b3, outp, M);
}

// round 13
// speedup vs baseline: 1.1345x; 1.1161x over previous
#include <cuda_runtime.h>
#include <cstdint>
#include <math.h>

#define N_NODES 50000
#define N_EDGES 1600000
#define FEAT 256
#define HID 256
#define OUTD 64

typedef unsigned long long ull;

// ---------- packed dual-fp32 FMA (f32x2; falls back to 2 FFMA if not fused) ----------
__device__ __forceinline__ void ffma2(ull& c, ull a, ull b) {
    asm("fma.rn.f32x2 %0, %1, %2, %0;" : "+l"(c) : "l"(a), "l"(b));
}
__device__ __forceinline__ ull bcast2(float x) {
    ull r;
    unsigned u = __float_as_uint(x);
    asm("mov.b64 %0, {%1, %1};" : "=l"(r) : "r"(u));
    return r;
}
__device__ __forceinline__ float2 unpack2(ull x) {
    float2 f;
    asm("mov.b64 {%0, %1}, %2;" : "=f"(f.x), "=f"(f.y) : "l"(x));
    return f;
}

// ---------------- scratch (device globals; no allocation) ----------------
__device__ int   g_cnt[N_NODES];
__device__ int   g_rowptr[N_NODES + 1];
__device__ int   g_cols[N_EDGES];
__device__ float g_wr[N_EDGES];
__device__ float g_wi[N_EDGES];
__device__ float g_Sr[N_NODES * FEAT];
__device__ float g_Si[N_NODES * FEAT];
__device__ float g_Hr[N_NODES * FEAT];
__device__ float g_Hi[N_NODES * FEAT];

// ---------------- CSR build ----------------
__global__ void zero_kernel() {
    int i = blockIdx.x * blockDim.x + threadIdx.x;
    if (i < N_NODES) g_cnt[i] = 0;
}
__global__ void hist_kernel(const int* __restrict__ row) {
    int e = blockIdx.x * blockDim.x + threadIdx.x;
    if (e < N_EDGES) atomicAdd(&g_cnt[row[e]], 1);
}
__global__ void scan_kernel() {
    __shared__ int s[1024];
    __shared__ int carry;
    int t = threadIdx.x;
    if (t == 0) carry = 0;
    __syncthreads();
    for (int base = 0; base < N_NODES; base += 1024) {
        int idx = base + t;
        int v = (idx < N_NODES) ? g_cnt[idx] : 0;
        s[t] = v;
        __syncthreads();
        for (int off = 1; off < 1024; off <<= 1) {
            int x = (t >= off) ? s[t - off] : 0;
            __syncthreads();
            s[t] += x;
            __syncthreads();
        }
        int excl = s[t] - v + carry;
        if (idx < N_NODES) { g_rowptr[idx] = excl; g_cnt[idx] = excl; }
        int tot = s[1023];
        __syncthreads();
        if (t == 0) carry += tot;
        __syncthreads();
    }
    if (t == 0) g_rowptr[N_NODES] = carry;
}
__global__ void scatter_kernel(const int* __restrict__ row, const int* __restrict__ col,
                               const float* __restrict__ ews, const float* __restrict__ ent,
                               const float* __restrict__ ccf, const float* __restrict__ q) {
    int e = blockIdx.x * blockDim.x + threadIdx.x;
    if (e >= N_EDGES) return;
    float phase = q[0] * (ent[e] + ccf[e]);
    float sn, cs;
    sincosf(phase, &sn, &cs);
    float w = ews[e];
    int pos = atomicAdd(&g_cnt[row[e]], 1);
    g_cols[pos] = col[e];
    g_wr[pos]   = w * cs;
    g_wi[pos]   = w * sn;
}

// ---------------- complex SPMM ----------------
__global__ void __launch_bounds__(256) spmm_kernel(const float* __restrict__ Xr,
                                                   const float* __restrict__ Xi,
                                                   float* __restrict__ Sr,
                                                   float* __restrict__ Si) {
    int node = blockIdx.x * 4 + threadIdx.y;
    if (node >= N_NODES) return;
    int t = threadIdx.x;  // 0..63
    const float4* Xr4 = (const float4*)Xr;
    const float4* Xi4 = (const float4*)Xi;
    float4 ar = make_float4(0.f, 0.f, 0.f, 0.f);
    float4 ai = make_float4(0.f, 0.f, 0.f, 0.f);
    int e = g_rowptr[node];
    int end = g_rowptr[node + 1];
#pragma unroll 2
    for (; e < end; e++) {
        int   c  = __ldg(&g_cols[e]);
        float wr = __ldg(&g_wr[e]);
        float wi = __ldg(&g_wi[e]);
        float4 xr = __ldg(&Xr4[c * 64 + t]);
        float4 xi = __ldg(&Xi4[c * 64 + t]);
        ar.x = fmaf(wr, xr.x, ar.x); ar.x = fmaf(-wi, xi.x, ar.x);
        ar.y = fmaf(wr, xr.y, ar.y); ar.y = fmaf(-wi, xi.y, ar.y);
        ar.z = fmaf(wr, xr.z, ar.z); ar.z = fmaf(-wi, xi.z, ar.z);
        ar.w = fmaf(wr, xr.w, ar.w); ar.w = fmaf(-wi, xi.w, ar.w);
        ai.x = fmaf(wi, xr.x, ai.x); ai.x = fmaf(wr, xi.x, ai.x);
        ai.y = fmaf(wi, xr.y, ai.y); ai.y = fmaf(wr, xi.y, ai.y);
        ai.z = fmaf(wi, xr.z, ai.z); ai.z = fmaf(wr, xi.z, ai.z);
        ai.w = fmaf(wi, xr.w, ai.w); ai.w = fmaf(wr, xi.w, ai.w);
    }
    ((float4*)Sr)[node * 64 + t] = ar;
    ((float4*)Si)[node * 64 + t] = ai;
}

// ================= fused layer GEMM =================
// Hr,Hi = ComReLU(Sr@W^T, Si@W^T + 2b)
// CTA tile 128m x 64n, 128 threads, per-thread 8x8 per component.
#define FBM 128
#define FBN 64
#define FBK 16

__global__ void __launch_bounds__(128, 2)
fused_layer_kernel(const float* __restrict__ Sr, const float* __restrict__ Si,
                   const float* __restrict__ W, const float* __restrict__ bias,
                   float* __restrict__ Hr, float* __restrict__ Hi, int M) {
    __shared__ __align__(16) float Asr[FBK][FBM];
    __shared__ __align__(16) float Asi[FBK][FBM];
    __shared__ __align__(16) float Ws[FBK][FBN];
    int tid = threadIdx.x;
    int m_base = blockIdx.x * FBM;
    int n_base = blockIdx.y * FBN;
    int tx = tid & 7, ty = tid >> 3;      // 8 n-groups x 16 m-groups
    int m0 = ty * 8, n0 = tx * 8;
    const float4* S4r = (const float4*)Sr;
    const float4* S4i = (const float4*)Si;
    const float4* W4  = (const float4*)W;

    ull accr[8][4], acci[8][4];
#pragma unroll
    for (int i = 0; i < 8; i++)
#pragma unroll
        for (int j = 0; j < 4; j++) { accr[i][j] = 0ull; acci[i][j] = 0ull; }

    float4 par[4], pai[4], pw[2];
    // prefetch chunk 0
#pragma unroll
    for (int it = 0; it < 4; it++) {
        int idx = tid + it * 128;
        int r = idx >> 2, kq = idx & 3;
        int gm = m_base + r;
        if (gm < M) {
            par[it] = __ldg(&S4r[gm * 64 + kq]);
            pai[it] = __ldg(&S4i[gm * 64 + kq]);
        } else {
            par[it] = make_float4(0.f, 0.f, 0.f, 0.f);
            pai[it] = make_float4(0.f, 0.f, 0.f, 0.f);
        }
    }
#pragma unroll
    for (int it = 0; it < 2; it++) {
        int idx = tid + it * 128;
        int r = idx >> 2, kq = idx & 3;
        pw[it] = __ldg(&W4[(n_base + r) * 64 + kq]);
    }

    for (int kc = 0; kc < 16; kc++) {
        // store current chunk to smem
#pragma unroll
        for (int it = 0; it < 4; it++) {
            int idx = tid + it * 128;
            int r = idx >> 2, kq = idx & 3;
            Asr[kq * 4 + 0][r] = par[it].x; Asr[kq * 4 + 1][r] = par[it].y;
            Asr[kq * 4 + 2][r] = par[it].z; Asr[kq * 4 + 3][r] = par[it].w;
            Asi[kq * 4 + 0][r] = pai[it].x; Asi[kq * 4 + 1][r] = pai[it].y;
            Asi[kq * 4 + 2][r] = pai[it].z; Asi[kq * 4 + 3][r] = pai[it].w;
        }
#pragma unroll
        for (int it = 0; it < 2; it++) {
            int idx = tid + it * 128;
            int r = idx >> 2, kq = idx & 3;
            Ws[kq * 4 + 0][r] = pw[it].x; Ws[kq * 4 + 1][r] = pw[it].y;
            Ws[kq * 4 + 2][r] = pw[it].z; Ws[kq * 4 + 3][r] = pw[it].w;
        }
        // prefetch next chunk into registers
        if (kc < 15) {
            int kf = (kc + 1) * 4;
#pragma unroll
            for (int it = 0; it < 4; it++) {
                int idx = tid + it * 128;
                int r = idx >> 2, kq = idx & 3;
                int gm = m_base + r;
                if (gm < M) {
                    par[it] = __ldg(&S4r[gm * 64 + kf + kq]);
                    pai[it] = __ldg(&S4i[gm * 64 + kf + kq]);
                } else {
                    par[it] = make_float4(0.f, 0.f, 0.f, 0.f);
                    pai[it] = make_float4(0.f, 0.f, 0.f, 0.f);
                }
            }
#pragma unroll
            for (int it = 0; it < 2; it++) {
                int idx = tid + it * 128;
                int r = idx >> 2, kq = idx & 3;
                pw[it] = __ldg(&W4[(n_base + r) * 64 + kf + kq]);
            }
        }
        __syncthreads();
        // compute this chunk
#pragma unroll
        for (int k = 0; k < FBK; k++) {
            float a_r[8], a_i[8];
            *(float4*)&a_r[0] = *(const float4*)&Asr[k][m0];
            *(float4*)&a_r[4] = *(const float4*)&Asr[k][m0 + 4];
            *(float4*)&a_i[0] = *(const float4*)&Asi[k][m0];
            *(float4*)&a_i[4] = *(const float4*)&Asi[k][m0 + 4];
            ulonglong2 b0 = *(const ulonglong2*)&Ws[k][n0];
            ulonglong2 b1 = *(const ulonglong2*)&Ws[k][n0 + 4];
#pragma unroll
            for (int i = 0; i < 8; i++) {
                ull vr = bcast2(a_r[i]);
                ffma2(accr[i][0], vr, b0.x);
                ffma2(accr[i][1], vr, b0.y);
                ffma2(accr[i][2], vr, b1.x);
                ffma2(accr[i][3], vr, b1.y);
                ull vi = bcast2(a_i[i]);
                ffma2(acci[i][0], vi, b0.x);
                ffma2(acci[i][1], vi, b0.y);
                ffma2(acci[i][2], vi, b1.x);
                ffma2(acci[i][3], vi, b1.y);
            }
        }
        __syncthreads();
    }

    // epilogue: bias (imag gets 2b), ComReLU mask, single write of both outputs
#pragma unroll
    for (int i = 0; i < 8; i++) {
        int gm = m_base + m0 + i;
        if (gm < M) {
#pragma unroll
            for (int jq = 0; jq < 2; jq++) {
                int gn = n_base + n0 + jq * 4;
                float2 r0 = unpack2(accr[i][jq * 2 + 0]);
                float2 r1 = unpack2(accr[i][jq * 2 + 1]);
                float2 q0 = unpack2(acci[i][jq * 2 + 0]);
                float2 q1 = unpack2(acci[i][jq * 2 + 1]);
                float4 bb = *(const float4*)&bias[gn];
                float pi0 = q0.x + 2.f * bb.x;
                float pi1 = q0.y + 2.f * bb.y;
                float pi2 = q1.x + 2.f * bb.z;
                float pi3 = q1.y + 2.f * bb.w;
                float m0f = (r0.x >= 0.f) ? 1.f : 0.f;
                float m1f = (r0.y >= 0.f) ? 1.f : 0.f;
                float m2f = (r1.x >= 0.f) ? 1.f : 0.f;
                float m3f = (r1.y >= 0.f) ? 1.f : 0.f;
                *(float4*)&Hr[gm * 256 + gn] =
                    make_float4(r0.x * m0f, r0.y * m1f, r1.x * m2f, r1.y * m3f);
                *(float4*)&Hi[gm * 256 + gn] =
                    make_float4(pi0 * m0f, pi1 * m1f, pi2 * m2f, pi3 * m3f);
            }
        }
    }
}

// ---------------- head: out = [Hr|Hi] @ W3^T + b3 ; M x 512 x 64 ----------------
#define HBM 128
#define HBK 16
__global__ void __launch_bounds__(256) head_kernel(const float* __restrict__ Ar,
                                                   const float* __restrict__ Ai,
                                                   const float* __restrict__ W,
                                                   const float* __restrict__ bias,
                                                   float* __restrict__ Cout, int M) {
    __shared__ __align__(16) float As[HBK][HBM];
    __shared__ __align__(16) float Bs[HBK][64];
    int tid = threadIdx.x;
    int m_base = blockIdx.x * HBM;
    int tx = tid & 15, ty = tid >> 4;
    int m0 = ty * 8, n0 = tx * 4;
    ull acc[8][2];
#pragma unroll
    for (int i = 0; i < 8; i++) {
        acc[i][0] = 0ull;
        acc[i][1] = 0ull;
    }

    for (int k0 = 0; k0 < 512; k0 += HBK) {
        const float* Asrc = (k0 < 256) ? Ar : Ai;
        int koff = k0 & 255;
#pragma unroll
        for (int it = 0; it < 2; it++) {
            int idx = tid + it * 256;
            int r = idx >> 2, kq = idx & 3;
            int gm = m_base + r;
            float4 v = make_float4(0.f, 0.f, 0.f, 0.f);
            if (gm < M) v = *(const float4*)&Asrc[gm * 256 + koff + kq * 4];
            As[kq * 4 + 0][r] = v.x; As[kq * 4 + 1][r] = v.y;
            As[kq * 4 + 2][r] = v.z; As[kq * 4 + 3][r] = v.w;
        }
        {
            int idx = tid;
            int r = idx >> 2, kq = idx & 3;
            float4 v = *(const float4*)&W[r * 512 + k0 + kq * 4];
            Bs[kq * 4 + 0][r] = v.x; Bs[kq * 4 + 1][r] = v.y;
            Bs[kq * 4 + 2][r] = v.z; Bs[kq * 4 + 3][r] = v.w;
        }
        __syncthreads();
#pragma unroll
        for (int k = 0; k < HBK; k++) {
            float a[8];
            *(float4*)&a[0] = *(const float4*)&As[k][m0];
            *(float4*)&a[4] = *(const float4*)&As[k][m0 + 4];
            ulonglong2 bA = *(const ulonglong2*)&Bs[k][n0];
#pragma unroll
            for (int i = 0; i < 8; i++) {
                ull ai = bcast2(a[i]);
                ffma2(acc[i][0], ai, bA.x);
                ffma2(acc[i][1], ai, bA.y);
            }
        }
        __syncthreads();
    }
    float4 bb = *(const float4*)&bias[n0];
#pragma unroll
    for (int i = 0; i < 8; i++) {
        int gm = m_base + m0 + i;
        if (gm < M) {
            float2 u0 = unpack2(acc[i][0]);
            float2 u1 = unpack2(acc[i][1]);
            *(float4*)&Cout[gm * OUTD + n0] =
                make_float4(u0.x + bb.x, u0.y + bb.y, u1.x + bb.z, u1.y + bb.w);
        }
    }
}

// ---------------- launch ----------------
extern "C" void kernel_launch(void* const* d_in, const int* in_sizes, int n_in,
                              void* d_out, int out_size) {
    const float* real_feature = (const float*)d_in[0];
    const float* imag_feature = (const float*)d_in[1];
    const int*   row          = (const int*)d_in[2];
    const int*   col          = (const int*)d_in[3];
    const float* ews          = (const float*)d_in[4];
    const float* ent          = (const float*)d_in[5];
    const float* ccf          = (const float*)d_in[6];
    const float* q            = (const float*)d_in[7];
    const float* W1           = (const float*)d_in[8];
    const float* b1           = (const float*)d_in[9];
    const float* W2           = (const float*)d_in[10];
    const float* b2           = (const float*)d_in[11];
    const float* W3           = (const float*)d_in[12];
    const float* b3           = (const float*)d_in[13];
    float* outp = (float*)d_out;

    float *pSr, *pSi, *pHr, *pHi;
    cudaGetSymbolAddress((void**)&pSr, g_Sr);
    cudaGetSymbolAddress((void**)&pSi, g_Si);
    cudaGetSymbolAddress((void**)&pHr, g_Hr);
    cudaGetSymbolAddress((void**)&pHi, g_Hi);

    const int M = N_NODES;
    int mb = (M + FBM - 1) / FBM;           // 391
    dim3 fused_grid(mb, HID / FBN, 1);      // (391, 4, 1)
    dim3 head_grid((M + HBM - 1) / HBM, 1, 1);
    dim3 spmm_grid((N_NODES + 3) / 4, 1, 1);
    dim3 spmm_block(64, 4, 1);

    // build dst-sorted CSR each launch
    zero_kernel<<<(N_NODES + 255) / 256, 256>>>();
    hist_kernel<<<(N_EDGES + 255) / 256, 256>>>(row);
    scan_kernel<<<1, 1024>>>();
    scatter_kernel<<<(N_EDGES + 255) / 256, 256>>>(row, col, ews, ent, ccf, q);

    // layer 1 (SPMM -> fused dual GEMM + ComReLU)
    spmm_kernel<<<spmm_grid, spmm_block>>>(real_feature, imag_feature, pSr, pSi);
    fused_layer_kernel<<<fused_grid, 128>>>(pSr, pSi, W1, b1, pHr, pHi, M);

    // layer 2
    spmm_kernel<<<spmm_grid, spmm_block>>>(pHr, pHi, pSr, pSi);
    fused_layer_kernel<<<fused_grid, 128>>>(pSr, pSi, W2, b2, pHr, pHi, M);

    // head
    head_kernel<<<head_grid, 256>>>(pHr, pHi, W3, b3, outp, M);
}

// round 14
// speedup vs baseline: 1.1398x; 1.0047x over previous
#include <cuda_runtime.h>
#include <cstdint>
#include <math.h>

#define N_NODES 50000
#define N_EDGES 1600000
#define FEAT 256
#define HID 256
#define OUTD 64

typedef unsigned long long ull;

// ---------- packed dual-fp32 FMA (f32x2) ----------
__device__ __forceinline__ void ffma2(ull& c, ull a, ull b) {
    asm("fma.rn.f32x2 %0, %1, %2, %0;" : "+l"(c) : "l"(a), "l"(b));
}
__device__ __forceinline__ ull bcast2(float x) {
    ull r;
    unsigned u = __float_as_uint(x);
    asm("mov.b64 %0, {%1, %1};" : "=l"(r) : "r"(u));
    return r;
}
__device__ __forceinline__ float2 unpack2(ull x) {
    float2 f;
    asm("mov.b64 {%0, %1}, %2;" : "=f"(f.x), "=f"(f.y) : "l"(x));
    return f;
}

// ---------------- scratch (device globals; no allocation) ----------------
#define SCAN_NB 49                       // ceil(50000/1024)
__device__ int    g_cnt[N_NODES];
__device__ int    g_rowptr[N_NODES + 1];
__device__ int    g_bsum[64];
__device__ int    g_bsumx[64];
__device__ float4 g_edges[N_EDGES];      // x=col(bits), y=wr, z=wi, w=pad
__device__ float  g_Sr[N_NODES * FEAT];
__device__ float  g_Si[N_NODES * FEAT];
__device__ float  g_Hr[N_NODES * FEAT];
__device__ float  g_Hi[N_NODES * FEAT];

// ---------------- CSR build ----------------
__global__ void zero_kernel() {
    int i = blockIdx.x * blockDim.x + threadIdx.x;
    if (i < N_NODES) g_cnt[i] = 0;
}
__global__ void hist_kernel(const int* __restrict__ row) {
    int e = blockIdx.x * blockDim.x + threadIdx.x;
    if (e < N_EDGES) atomicAdd(&g_cnt[row[e]], 1);
}
// hierarchical exclusive scan of g_cnt -> g_rowptr (+cursor copy in g_cnt)
__global__ void scan1_kernel() {
    __shared__ int s[1024];
    int b = blockIdx.x, t = threadIdx.x;
    int idx = b * 1024 + t;
    int v = (idx < N_NODES) ? g_cnt[idx] : 0;
    s[t] = v;
    __syncthreads();
#pragma unroll
    for (int off = 1; off < 1024; off <<= 1) {
        int x = (t >= off) ? s[t - off] : 0;
        __syncthreads();
        s[t] += x;
        __syncthreads();
    }
    if (idx < N_NODES) g_rowptr[idx] = s[t] - v;   // block-local exclusive
    if (t == 1023) g_bsum[b] = s[1023];
}
__global__ void scan2_kernel() {
    __shared__ int s[64];
    int t = threadIdx.x;
    int v = (t < SCAN_NB) ? g_bsum[t] : 0;
    s[t] = v;
    __syncthreads();
#pragma unroll
    for (int off = 1; off < 64; off <<= 1) {
        int x = (t >= off) ? s[t - off] : 0;
        __syncthreads();
        s[t] += x;
        __syncthreads();
    }
    g_bsumx[t] = s[t] - v;                          // exclusive
    if (t == SCAN_NB - 1) g_rowptr[N_NODES] = s[t]; // total
}
__global__ void scan3_kernel() {
    int b = blockIdx.x, t = threadIdx.x;
    int idx = b * 1024 + t;
    if (idx < N_NODES) {
        int v = g_rowptr[idx] + g_bsumx[b];
        g_rowptr[idx] = v;
        g_cnt[idx] = v;                             // scatter cursor
    }
}
__global__ void scatter_kernel(const int* __restrict__ row, const int* __restrict__ col,
                               const float* __restrict__ ews, const float* __restrict__ ent,
                               const float* __restrict__ ccf, const float* __restrict__ q) {
    int e = blockIdx.x * blockDim.x + threadIdx.x;
    if (e >= N_EDGES) return;
    float phase = q[0] * (ent[e] + ccf[e]);
    float sn, cs;
    sincosf(phase, &sn, &cs);
    float w = ews[e];
    int pos = atomicAdd(&g_cnt[row[e]], 1);
    g_edges[pos] = make_float4(__int_as_float(col[e]), w * cs, w * sn, 0.f);
}

// ---------------- complex SPMM ----------------
__global__ void __launch_bounds__(256) spmm_kernel(const float* __restrict__ Xr,
                                                   const float* __restrict__ Xi,
                                                   float* __restrict__ Sr,
                                                   float* __restrict__ Si) {
    int node = blockIdx.x * 4 + threadIdx.y;
    if (node >= N_NODES) return;
    int t = threadIdx.x;  // 0..63
    const float4* Xr4 = (const float4*)Xr;
    const float4* Xi4 = (const float4*)Xi;
    float4 ar = make_float4(0.f, 0.f, 0.f, 0.f);
    float4 ai = make_float4(0.f, 0.f, 0.f, 0.f);
    int e = g_rowptr[node];
    int end = g_rowptr[node + 1];
#pragma unroll 4
    for (; e < end; e++) {
        float4 ed = __ldg(&g_edges[e]);
        int   c  = __float_as_int(ed.x);
        float wr = ed.y;
        float wi = ed.z;
        float4 xr = __ldg(&Xr4[c * 64 + t]);
        float4 xi = __ldg(&Xi4[c * 64 + t]);
        ar.x = fmaf(wr, xr.x, ar.x); ar.x = fmaf(-wi, xi.x, ar.x);
        ar.y = fmaf(wr, xr.y, ar.y); ar.y = fmaf(-wi, xi.y, ar.y);
        ar.z = fmaf(wr, xr.z, ar.z); ar.z = fmaf(-wi, xi.z, ar.z);
        ar.w = fmaf(wr, xr.w, ar.w); ar.w = fmaf(-wi, xi.w, ar.w);
        ai.x = fmaf(wi, xr.x, ai.x); ai.x = fmaf(wr, xi.x, ai.x);
        ai.y = fmaf(wi, xr.y, ai.y); ai.y = fmaf(wr, xi.y, ai.y);
        ai.z = fmaf(wi, xr.z, ai.z); ai.z = fmaf(wr, xi.z, ai.z);
        ai.w = fmaf(wi, xr.w, ai.w); ai.w = fmaf(wr, xi.w, ai.w);
    }
    ((float4*)Sr)[node * 64 + t] = ar;
    ((float4*)Si)[node * 64 + t] = ai;
}

// ================= fused layer GEMM =================
// Hr,Hi = ComReLU(Sr@W^T, Si@W^T + 2b)
// CTA tile 128m x 64n, 128 threads, per-thread 8x8 per component.
#define FBM 128
#define FBN 64
#define FBK 16

__global__ void __launch_bounds__(128, 2)
fused_layer_kernel(const float* __restrict__ Sr, const float* __restrict__ Si,
                   const float* __restrict__ W, const float* __restrict__ bias,
                   float* __restrict__ Hr, float* __restrict__ Hi, int M) {
    __shared__ __align__(16) float Asr[FBK][FBM];
    __shared__ __align__(16) float Asi[FBK][FBM];
    __shared__ __align__(16) float Ws[FBK][FBN];
    int tid = threadIdx.x;
    int m_base = blockIdx.x * FBM;
    int n_base = blockIdx.y * FBN;
    int tx = tid & 7, ty = tid >> 3;      // 8 n-groups x 16 m-groups
    int m0 = ty * 8, n0 = tx * 8;
    const float4* S4r = (const float4*)Sr;
    const float4* S4i = (const float4*)Si;
    const float4* W4  = (const float4*)W;

    ull accr[8][4], acci[8][4];
#pragma unroll
    for (int i = 0; i < 8; i++)
#pragma unroll
        for (int j = 0; j < 4; j++) { accr[i][j] = 0ull; acci[i][j] = 0ull; }

    float4 par[4], pai[4], pw[2];
    // prefetch chunk 0
#pragma unroll
    for (int it = 0; it < 4; it++) {
        int idx = tid + it * 128;
        int r = idx >> 2, kq = idx & 3;
        int gm = m_base + r;
        if (gm < M) {
            par[it] = __ldg(&S4r[gm * 64 + kq]);
            pai[it] = __ldg(&S4i[gm * 64 + kq]);
        } else {
            par[it] = make_float4(0.f, 0.f, 0.f, 0.f);
            pai[it] = make_float4(0.f, 0.f, 0.f, 0.f);
        }
    }
#pragma unroll
    for (int it = 0; it < 2; it++) {
        int idx = tid + it * 128;
        int r = idx >> 2, kq = idx & 3;
        pw[it] = __ldg(&W4[(n_base + r) * 64 + kq]);
    }

    for (int kc = 0; kc < 16; kc++) {
        // store current chunk to smem
#pragma unroll
        for (int it = 0; it < 4; it++) {
            int idx = tid + it * 128;
            int r = idx >> 2, kq = idx & 3;
            Asr[kq * 4 + 0][r] = par[it].x; Asr[kq * 4 + 1][r] = par[it].y;
            Asr[kq * 4 + 2][r] = par[it].z; Asr[kq * 4 + 3][r] = par[it].w;
            Asi[kq * 4 + 0][r] = pai[it].x; Asi[kq * 4 + 1][r] = pai[it].y;
            Asi[kq * 4 + 2][r] = pai[it].z; Asi[kq * 4 + 3][r] = pai[it].w;
        }
#pragma unroll
        for (int it = 0; it < 2; it++) {
            int idx = tid + it * 128;
            int r = idx >> 2, kq = idx & 3;
            Ws[kq * 4 + 0][r] = pw[it].x; Ws[kq * 4 + 1][r] = pw[it].y;
            Ws[kq * 4 + 2][r] = pw[it].z; Ws[kq * 4 + 3][r] = pw[it].w;
        }
        // prefetch next chunk into registers
        if (kc < 15) {
            int kf = (kc + 1) * 4;
#pragma unroll
            for (int it = 0; it < 4; it++) {
                int idx = tid + it * 128;
                int r = idx >> 2, kq = idx & 3;
                int gm = m_base + r;
                if (gm < M) {
                    par[it] = __ldg(&S4r[gm * 64 + kf + kq]);
                    pai[it] = __ldg(&S4i[gm * 64 + kf + kq]);
                } else {
                    par[it] = make_float4(0.f, 0.f, 0.f, 0.f);
                    pai[it] = make_float4(0.f, 0.f, 0.f, 0.f);
                }
            }
#pragma unroll
            for (int it = 0; it < 2; it++) {
                int idx = tid + it * 128;
                int r = idx >> 2, kq = idx & 3;
                pw[it] = __ldg(&W4[(n_base + r) * 64 + kf + kq]);
            }
        }
        __syncthreads();
        // compute this chunk
#pragma unroll
        for (int k = 0; k < FBK; k++) {
            float a_r[8], a_i[8];
            *(float4*)&a_r[0] = *(const float4*)&Asr[k][m0];
            *(float4*)&a_r[4] = *(const float4*)&Asr[k][m0 + 4];
            *(float4*)&a_i[0] = *(const float4*)&Asi[k][m0];
            *(float4*)&a_i[4] = *(const float4*)&Asi[k][m0 + 4];
            ulonglong2 b0 = *(const ulonglong2*)&Ws[k][n0];
            ulonglong2 b1 = *(const ulonglong2*)&Ws[k][n0 + 4];
#pragma unroll
            for (int i = 0; i < 8; i++) {
                ull vr = bcast2(a_r[i]);
                ffma2(accr[i][0], vr, b0.x);
                ffma2(accr[i][1], vr, b0.y);
                ffma2(accr[i][2], vr, b1.x);
                ffma2(accr[i][3], vr, b1.y);
                ull vi = bcast2(a_i[i]);
                ffma2(acci[i][0], vi, b0.x);
                ffma2(acci[i][1], vi, b0.y);
                ffma2(acci[i][2], vi, b1.x);
                ffma2(acci[i][3], vi, b1.y);
            }
        }
        __syncthreads();
    }

    // epilogue: bias (imag gets 2b), ComReLU mask, single write of both outputs
#pragma unroll
    for (int i = 0; i < 8; i++) {
        int gm = m_base + m0 + i;
        if (gm < M) {
#pragma unroll
            for (int jq = 0; jq < 2; jq++) {
                int gn = n_base + n0 + jq * 4;
                float2 r0 = unpack2(accr[i][jq * 2 + 0]);
                float2 r1 = unpack2(accr[i][jq * 2 + 1]);
                float2 q0 = unpack2(acci[i][jq * 2 + 0]);
                float2 q1 = unpack2(acci[i][jq * 2 + 1]);
                float4 bb = *(const float4*)&bias[gn];
                float pi0 = q0.x + 2.f * bb.x;
                float pi1 = q0.y + 2.f * bb.y;
                float pi2 = q1.x + 2.f * bb.z;
                float pi3 = q1.y + 2.f * bb.w;
                float m0f = (r0.x >= 0.f) ? 1.f : 0.f;
                float m1f = (r0.y >= 0.f) ? 1.f : 0.f;
                float m2f = (r1.x >= 0.f) ? 1.f : 0.f;
                float m3f = (r1.y >= 0.f) ? 1.f : 0.f;
                *(float4*)&Hr[gm * 256 + gn] =
                    make_float4(r0.x * m0f, r0.y * m1f, r1.x * m2f, r1.y * m3f);
                *(float4*)&Hi[gm * 256 + gn] =
                    make_float4(pi0 * m0f, pi1 * m1f, pi2 * m2f, pi3 * m3f);
            }
        }
    }
}

// ---------------- head: out = [Hr|Hi] @ W3^T + b3 ; M x 512 x 64 ----------------
#define HBM 128
#define HBK 16
__global__ void __launch_bounds__(256) head_kernel(const float* __restrict__ Ar,
                                                   const float* __restrict__ Ai,
                                                   const float* __restrict__ W,
                                                   const float* __restrict__ bias,
                                                   float* __restrict__ Cout, int M) {
    __shared__ __align__(16) float As[HBK][HBM];
    __shared__ __align__(16) float Bs[HBK][64];
    int tid = threadIdx.x;
    int m_base = blockIdx.x * HBM;
    int tx = tid & 15, ty = tid >> 4;
    int m0 = ty * 8, n0 = tx * 4;
    ull acc[8][2];
#pragma unroll
    for (int i = 0; i < 8; i++) {
        acc[i][0] = 0ull;
        acc[i][1] = 0ull;
    }

    for (int k0 = 0; k0 < 512; k0 += HBK) {
        const float* Asrc = (k0 < 256) ? Ar : Ai;
        int koff = k0 & 255;
#pragma unroll
        for (int it = 0; it < 2; it++) {
            int idx = tid + it * 256;
            int r = idx >> 2, kq = idx & 3;
            int gm = m_base + r;
            float4 v = make_float4(0.f, 0.f, 0.f, 0.f);
            if (gm < M) v = *(const float4*)&Asrc[gm * 256 + koff + kq * 4];
            As[kq * 4 + 0][r] = v.x; As[kq * 4 + 1][r] = v.y;
            As[kq * 4 + 2][r] = v.z; As[kq * 4 + 3][r] = v.w;
        }
        {
            int idx = tid;
            int r = idx >> 2, kq = idx & 3;
            float4 v = *(const float4*)&W[r * 512 + k0 + kq * 4];
            Bs[kq * 4 + 0][r] = v.x; Bs[kq * 4 + 1][r] = v.y;
            Bs[kq * 4 + 2][r] = v.z; Bs[kq * 4 + 3][r] = v.w;
        }
        __syncthreads();
#pragma unroll
        for (int k = 0; k < HBK; k++) {
            float a[8];
            *(float4*)&a[0] = *(const float4*)&As[k][m0];
            *(float4*)&a[4] = *(const float4*)&As[k][m0 + 4];
            ulonglong2 bA = *(const ulonglong2*)&Bs[k][n0];
#pragma unroll
            for (int i = 0; i < 8; i++) {
                ull ai = bcast2(a[i]);
                ffma2(acc[i][0], ai, bA.x);
                ffma2(acc[i][1], ai, bA.y);
            }
        }
        __syncthreads();
    }
    float4 bb = *(const float4*)&bias[n0];
#pragma unroll
    for (int i = 0; i < 8; i++) {
        int gm = m_base + m0 + i;
        if (gm < M) {
            float2 u0 = unpack2(acc[i][0]);
            float2 u1 = unpack2(acc[i][1]);
            *(float4*)&Cout[gm * OUTD + n0] =
                make_float4(u0.x + bb.x, u0.y + bb.y, u1.x + bb.z, u1.y + bb.w);
        }
    }
}

// ---------------- launch ----------------
extern "C" void kernel_launch(void* const* d_in, const int* in_sizes, int n_in,
                              void* d_out, int out_size) {
    const float* real_feature = (const float*)d_in[0];
    const float* imag_feature = (const float*)d_in[1];
    const int*   row          = (const int*)d_in[2];
    const int*   col          = (const int*)d_in[3];
    const float* ews          = (const float*)d_in[4];
    const float* ent          = (const float*)d_in[5];
    const float* ccf          = (const float*)d_in[6];
    const float* q            = (const float*)d_in[7];
    const float* W1           = (const float*)d_in[8];
    const float* b1           = (const float*)d_in[9];
    const float* W2           = (const float*)d_in[10];
    const float* b2           = (const float*)d_in[11];
    const float* W3           = (const float*)d_in[12];
    const float* b3           = (const float*)d_in[13];
    float* outp = (float*)d_out;

    float *pSr, *pSi, *pHr, *pHi;
    cudaGetSymbolAddress((void**)&pSr, g_Sr);
    cudaGetSymbolAddress((void**)&pSi, g_Si);
    cudaGetSymbolAddress((void**)&pHr, g_Hr);
    cudaGetSymbolAddress((void**)&pHi, g_Hi);

    const int M = N_NODES;
    int mb = (M + FBM - 1) / FBM;           // 391
    dim3 fused_grid(mb, HID / FBN, 1);      // (391, 4, 1)
    dim3 head_grid((M + HBM - 1) / HBM, 1, 1);
    dim3 spmm_grid((N_NODES + 3) / 4, 1, 1);
    dim3 spmm_block(64, 4, 1);

    // build dst-sorted CSR each launch
    zero_kernel<<<(N_NODES + 255) / 256, 256>>>();
    hist_kernel<<<(N_EDGES + 255) / 256, 256>>>(row);
    scan1_kernel<<<SCAN_NB, 1024>>>();
    scan2_kernel<<<1, 64>>>();
    scan3_kernel<<<SCAN_NB, 1024>>>();
    scatter_kernel<<<(N_EDGES + 255) / 256, 256>>>(row, col, ews, ent, ccf, q);

    // layer 1 (SPMM -> fused dual GEMM + ComReLU)
    spmm_kernel<<<spmm_grid, spmm_block>>>(real_feature, imag_feature, pSr, pSi);
    fused_layer_kernel<<<fused_grid, 128>>>(pSr, pSi, W1, b1, pHr, pHi, M);

    // layer 2
    spmm_kernel<<<spmm_grid, spmm_block>>>(pHr, pHi, pSr, pSi);
    fused_layer_kernel<<<fused_grid, 128>>>(pSr, pSi, W2, b2, pHr, pHi, M);

    // head
    head_kernel<<<head_grid, 256>>>(pHr, pHi, W3, b3, outp, M);
}